// round 4
// baseline (speedup 1.0000x reference)
#include <cuda_runtime.h>
#include <math.h>

#define BATCH 4
#define NPTS  8192
#define NSPLIT 16
#define BRANGE (NPTS / NSPLIT)            // 512 label points per block
#define NPAIR  (BRANGE / 2)               // 256 packed col-pairs
#define PTS_PER_THREAD 8
#define THREADS 64
#define ROWS_PER_BLOCK (THREADS * PTS_PER_THREAD)  // 512
#define NCHUNK (NPTS / ROWS_PER_BLOCK)             // 16
#define FIN_THREADS 256
#define FIN_BLOCKS ((2 * BATCH * NPTS) / FIN_THREADS)  // 256

// Per-point running max of (x.y - ||other||^2/2), monotonic-uint encoded.
// Zero-init == "-inf" under the encoding (any real value encodes > 0).
__device__ unsigned g_rmax[BATCH * NPTS];   // rows  = pred  -> label
__device__ unsigned g_cmax[BATCH * NPTS];   // cols  = label -> pred
__device__ float    g_bsum[FIN_BLOCKS];
__device__ unsigned g_counter = 0;

typedef unsigned long long ull;
union U64F2 { ull u; float2 f; };

__device__ __forceinline__ ull fma2(ull a, ull b, ull c) {
    ull d; asm("fma.rn.f32x2 %0, %1, %2, %3;" : "=l"(d) : "l"(a), "l"(b), "l"(c)); return d;
}
__device__ __forceinline__ ull mul2(ull a, ull b) {
    ull d; asm("mul.rn.f32x2 %0, %1, %2;" : "=l"(d) : "l"(a), "l"(b)); return d;
}
__device__ __forceinline__ ull add2(ull a, ull b) {
    ull d; asm("add.rn.f32x2 %0, %1, %2;" : "=l"(d) : "l"(a), "l"(b)); return d;
}
__device__ __forceinline__ ull pack2(float lo, float hi) {
    U64F2 u; u.f = make_float2(lo, hi); return u.u;
}
__device__ __forceinline__ float lof(ull v) { U64F2 u; u.u = v; return u.f.x; }
__device__ __forceinline__ float hif(ull v) { U64F2 u; u.u = v; return u.f.y; }

// Order-preserving float -> uint encoding (for atomicMax).
__device__ __forceinline__ unsigned enc(float f) {
    unsigned u = __float_as_uint(f);
    return u ^ ((unsigned)((int)u >> 31) | 0x80000000u);
}
__device__ __forceinline__ float dec(unsigned k) {
    unsigned u = (k & 0x80000000u) ? (k ^ 0x80000000u) : ~k;
    return __uint_as_float(u);
}

// One block: 512 pred rows x 512 label cols of one batch's dot matrix.
// blockIdx.x = row chunk, blockIdx.y = batch, blockIdx.z = col split.
__global__ __launch_bounds__(THREADS)
void chamfer_main(const float* __restrict__ pred,
                  const float* __restrict__ label) {
    const int split = blockIdx.z;
    const int b     = blockIdx.y;
    const float* __restrict__ A  = pred  + (size_t)b * NPTS * 3;
    const float* __restrict__ Bt = label + (size_t)b * NPTS * 3
                                         + (size_t)split * BRANGE * 3;

    // Pair layout: slot 2q = (bx0,bx1,by0,by1), slot 2q+1 = (bz0,bz1,wy0,wy1)
    __shared__ float4 sB[BRANGE];   // 8 KB

    const int tid = threadIdx.x;

    #pragma unroll
    for (int q = tid; q < NPAIR; q += THREADS) {
        const float* p = Bt + 6 * q;
        const float bx0 = p[0], by0 = p[1], bz0 = p[2];
        const float bx1 = p[3], by1 = p[4], bz1 = p[5];
        const float wy0 = -0.5f * fmaf(bx0, bx0, fmaf(by0, by0, bz0 * bz0));
        const float wy1 = -0.5f * fmaf(bx1, bx1, fmaf(by1, by1, bz1 * bz1));
        sB[2 * q]     = make_float4(bx0, bx1, by0, by1);
        sB[2 * q + 1] = make_float4(bz0, bz1, wy0, wy1);
    }

    // Per-thread pred rows: duplicated f32x2 coords + wx = -||x||^2/2
    ull ax2[PTS_PER_THREAD], ay2[PTS_PER_THREAD], az2[PTS_PER_THREAD], wx2[PTS_PER_THREAD];
    float m0[PTS_PER_THREAD], m1[PTS_PER_THREAD];
    const int row0 = blockIdx.x * ROWS_PER_BLOCK + tid;
    #pragma unroll
    for (int p = 0; p < PTS_PER_THREAD; p++) {
        const int i = row0 + p * THREADS;
        const float ax = A[i * 3 + 0];
        const float ay = A[i * 3 + 1];
        const float az = A[i * 3 + 2];
        const float wx = -0.5f * fmaf(ax, ax, fmaf(ay, ay, az * az));
        ax2[p] = pack2(ax, ax);
        ay2[p] = pack2(ay, ay);
        az2[p] = pack2(az, az);
        wx2[p] = pack2(wx, wx);
        m0[p] = -3.0e38f;
        m1[p] = -3.0e38f;
    }
    __syncthreads();

    const ulonglong2* __restrict__ sB64 = (const ulonglong2*)sB;
    const int lane = tid & 31;
    const size_t colbase = (size_t)b * NPTS + (size_t)split * BRANGE;

    #pragma unroll 2
    for (int q = 0; q < NPAIR; q++) {
        const ulonglong2 v0 = sB64[2 * q];       // (bx0,bx1) (by0,by1)
        const ulonglong2 v1 = sB64[2 * q + 1];   // (bz0,bz1) (wy0,wy1)
        float c0 = -3.0e38f, c1 = -3.0e38f;
        #pragma unroll
        for (int p = 0; p < PTS_PER_THREAD; p++) {
            ull t = mul2(v1.x, az2[p]);          // bz*az
            t = fma2(v0.y, ay2[p], t);           // + by*ay
            t = fma2(v0.x, ax2[p], t);           // + bx*ax
            const ull s = add2(t, v1.y);         // row side: t - ||y||^2/2
            const ull u = add2(t, wx2[p]);       // col side: t - ||x||^2/2
            m0[p] = fmaxf(m0[p], lof(s));
            m1[p] = fmaxf(m1[p], hif(s));
            c0 = fmaxf(c0, lof(u));
            c1 = fmaxf(c1, hif(u));
        }
        // Warp-reduce col maxes, lane 0 fires no-return global atomics.
        #pragma unroll
        for (int off = 16; off > 0; off >>= 1) {
            c0 = fmaxf(c0, __shfl_xor_sync(0xFFFFFFFFu, c0, off));
            c1 = fmaxf(c1, __shfl_xor_sync(0xFFFFFFFFu, c1, off));
        }
        if (lane == 0) {
            atomicMax(&g_cmax[colbase + 2 * q],     enc(c0));
            atomicMax(&g_cmax[colbase + 2 * q + 1], enc(c1));
        }
    }

    // Flush row maxes (one slot per pred point, merged across col splits).
    #pragma unroll
    for (int p = 0; p < PTS_PER_THREAD; p++) {
        atomicMax(&g_rmax[(size_t)b * NPTS + row0 + p * THREADS],
                  enc(fmaxf(m0[p], m1[p])));
    }
}

// One thread per (dir, batch, point): decode max, sqrt, reduce to scalar.
// Also resets the accumulators so graph replays are deterministic.
__global__ __launch_bounds__(FIN_THREADS)
void chamfer_finalize(const float* __restrict__ pred,
                      const float* __restrict__ label,
                      float* __restrict__ out) {
    const int idx = blockIdx.x * FIN_THREADS + threadIdx.x;   // 0 .. 65535
    const int dir = idx >> 15;
    const int rem = idx & 32767;                               // b*NPTS + i
    const float* __restrict__ P = ((dir == 0) ? pred : label) + (size_t)rem * 3;
    unsigned* __restrict__ g = (dir == 0) ? g_rmax : g_cmax;

    const float ax = P[0], ay = P[1], az = P[2];
    const float x2 = fmaf(ax, ax, fmaf(ay, ay, az * az));
    const float m = dec(g[rem]);
    g[rem] = 0u;    // reset for next replay
    const float d = sqrtf(fmaxf(fmaf(-2.0f, m, x2), 0.0f));
    float s = d;

    #pragma unroll
    for (int off = 16; off > 0; off >>= 1)
        s += __shfl_down_sync(0xFFFFFFFFu, s, off);

    __shared__ float warp_sums[FIN_THREADS / 32];
    __shared__ bool is_last;
    const int tid = threadIdx.x;
    if ((tid & 31) == 0) warp_sums[tid >> 5] = s;
    __syncthreads();
    if (tid == 0) {
        float bs = 0.0f;
        #pragma unroll
        for (int w = 0; w < FIN_THREADS / 32; w++) bs += warp_sums[w];
        g_bsum[blockIdx.x] = bs;
        __threadfence();
        const unsigned done = atomicAdd(&g_counter, 1u) + 1u;
        is_last = (done == FIN_BLOCKS);
    }
    __syncthreads();

    if (is_last) {
        float v = g_bsum[tid];   // FIN_THREADS == FIN_BLOCKS
        #pragma unroll
        for (int off = 16; off > 0; off >>= 1)
            v += __shfl_down_sync(0xFFFFFFFFu, v, off);
        if ((tid & 31) == 0) warp_sums[tid >> 5] = v;
        __syncthreads();
        if (tid == 0) {
            float tot = 0.0f;
            #pragma unroll
            for (int w = 0; w < FIN_THREADS / 32; w++) tot += warp_sums[w];
            out[0] = tot * (1.0f / (float)(BATCH * NPTS));
            g_counter = 0u;
        }
    }
}

extern "C" void kernel_launch(void* const* d_in, const int* in_sizes, int n_in,
                              void* d_out, int out_size) {
    const float* pred  = (const float*)d_in[0];
    const float* label = (const float*)d_in[1];
    float* out = (float*)d_out;

    dim3 grid(NCHUNK, BATCH, NSPLIT);   // 16 x 4 x 16 = 1024 blocks
    chamfer_main<<<grid, THREADS>>>(pred, label);
    chamfer_finalize<<<FIN_BLOCKS, FIN_THREADS>>>(pred, label, out);
}